// round 9
// baseline (speedup 1.0000x reference)
#include <cuda_runtime.h>
#include <cuda_bf16.h>
#include <cstdint>

// Problem constants: B=32, N=8192, C=512, K=128
#define PB    32
#define PN    8192
#define PC    512
#define PK    128
#define SEGS  32        // CTAs per batch
#define TPB   256       // threads per CTA = elements per CTA (SEGS*TPB = PN)
#define WORDS 256       // bitmask words per batch (PN/32)

// Scratch (zero-init at module load; finisher restores zeros every launch).
__device__ unsigned int g_mask[PB * WORDS];
__device__ unsigned int g_done[PB];

__global__ void __launch_bounds__(TPB) fused_filter_kernel(
    const float* __restrict__ one_hot,
    const int*   __restrict__ id_ptr,
    float*       __restrict__ out)
{
    const int g    = blockIdx.x;         // 0 .. PB*SEGS-1
    const int b    = g >> 5;             // batch
    const int seg  = g & (SEGS - 1);     // segment within batch
    const int t    = threadIdx.x;
    const int lane = t & 31;
    const int wid  = t >> 5;             // 0..7

    const int id = __ldg(id_ptr);
    const int n  = seg * TPB + t;        // position within batch
    const size_t idx = (size_t)b * PN + n;

    // ---- scattered gather via cp.async (LDGSTS): no register-return MSHR
    //      tracking, so the SM can keep far more line-misses in flight.
    __shared__ float s_val[TPB];
    {
        const float* src = one_hot + idx * PC + id;
        uint32_t saddr;
        asm("{ .reg .u64 a; cvta.to.shared.u64 a, %1; cvt.u32.u64 %0, a; }"
            : "=r"(saddr) : "l"(&s_val[t]));
        asm volatile("cp.async.ca.shared.global [%0], [%1], 4;"
                     :: "r"(saddr), "l"(src) : "memory");
        asm volatile("cp.async.commit_group;" ::: "memory");
        asm volatile("cp.async.wait_group 0;" ::: "memory");
    }
    float v = s_val[t];                  // own slot; own copy complete after wait

    // ---- block_id output (coalesced; never fenced) ----
    out[idx] = v;

    // ---- stage hit via bitmask atomic; consume return so the update is
    //      performed at L2 before this thread reaches the barrier.
    if (v != 0.0f) {
        unsigned old = atomicOr(&g_mask[b * WORDS + (n >> 5)], 1u << (n & 31));
        if (old == 0xFFFFFFFFu) out[idx] = v;   // impossible; consumes 'old'
    }

    __syncthreads();                      // all staging atomics complete (L2)

    __shared__ unsigned s_done;
    if (t == 0) s_done = atomicAdd(&g_done[b], 1u);
    __syncthreads();

    if (s_done != SEGS - 1) return;       // not the last CTA of this batch

    // ========== finisher CTA for batch b (wait-free: all others done) ======
    __threadfence();                      // acquire; single CTA, cheap

    // Each thread owns one 32-bit mask word = positions [t*32, t*32+32)
    unsigned w = __ldcg(&g_mask[b * WORDS + t]);
    int cnt = __popc(w);

    // Inclusive warp scan of per-word counts
    int inc = cnt;
#pragma unroll
    for (int d = 1; d < 32; d <<= 1) {
        int y = __shfl_up_sync(0xffffffffu, inc, d);
        if (lane >= d) inc += y;
    }

    __shared__ int s_wsum[8];
    if (lane == 31) s_wsum[wid] = inc;
    __syncthreads();

    if (wid == 0) {
        int wv = (lane < 8) ? s_wsum[lane] : 0;
        int winc = wv;
#pragma unroll
        for (int d = 1; d < 8; d <<= 1) {
            int y = __shfl_up_sync(0xffffffffu, winc, d);
            if (lane >= d) winc += y;
        }
        if (lane < 8) s_wsum[lane] = winc - wv;   // exclusive warp base
    }
    __syncthreads();

    int pos = s_wsum[wid] + (inc - cnt);          // exclusive thread base

    // Emit set-bit positions in ascending order (bitmask => sorted for free)
    float* oidx = out + (size_t)PB * PN + (size_t)b * PK;
    while (w) {
        int bit = __ffs(w) - 1;
        w &= w - 1;
        if (pos < PK) oidx[pos] = (float)(t * 32 + bit);
        pos++;
    }

    // ---- reset scratch for the next graph replay ----
    g_mask[b * WORDS + t] = 0u;
    if (t == 0) g_done[b] = 0u;
}

extern "C" void kernel_launch(void* const* d_in, const int* in_sizes, int n_in,
                              void* d_out, int out_size)
{
    const float* one_hot = (const float*)d_in[0];
    const int*   id_ptr  = (const int*)d_in[1];
    float*       out     = (float*)d_out;

    (void)in_sizes; (void)n_in; (void)out_size;

    fused_filter_kernel<<<PB * SEGS, TPB>>>(one_hot, id_ptr, out);
}

// round 11
// speedup vs baseline: 1.0959x; 1.0959x over previous
#include <cuda_runtime.h>
#include <cuda_bf16.h>
#include <cstdint>

// Problem constants: B=32, N=8192, C=512, K=128
#define PB    32
#define PN    8192
#define PC    512
#define PK    128
#define SEGS  32        // CTAs per batch
#define TPB   256       // threads per CTA = elements per CTA (SEGS*TPB = PN)
#define WORDS 256       // bitmask words per batch (PN/32)

// Scratch (zero-init at module load; finisher restores zeros every launch).
__device__ unsigned int g_mask[PB * WORDS];
__device__ unsigned int g_done[PB];

__global__ void __launch_bounds__(TPB) fused_filter_kernel(
    const float* __restrict__ one_hot,
    const int*   __restrict__ id_ptr,
    float*       __restrict__ out)
{
    const int g    = blockIdx.x;         // 0 .. PB*SEGS-1
    const int b    = g >> 5;             // batch
    const int seg  = g & (SEGS - 1);     // segment within batch
    const int t    = threadIdx.x;
    const int lane = t & 31;
    const int wid  = t >> 5;             // 0..7

    const int id = __ldg(id_ptr);
    const int n  = seg * TPB + t;        // position within batch
    const size_t idx = (size_t)b * PN + n;

    // ---- scattered gather: ld.global.cg = L2-only, sector-granular.
    //      (__ldg/.nc promoted every miss to a full 128B DRAM line fetch —
    //       measured 33.5MB traffic for 8.4MB of useful sectors.)
    float v = __ldcg(one_hot + idx * PC + id);

    // ---- block_id output (coalesced; never fenced) ----
    out[idx] = v;

    // ---- stage hit via bitmask atomic; consume return so the update is
    //      performed at L2 before this thread reaches the barrier.
    if (v != 0.0f) {
        unsigned old = atomicOr(&g_mask[b * WORDS + (n >> 5)], 1u << (n & 31));
        if (old == 0xFFFFFFFFu) out[idx] = v;   // impossible; consumes 'old'
    }

    __syncthreads();                      // all staging atomics complete (L2)

    __shared__ unsigned s_done;
    if (t == 0) s_done = atomicAdd(&g_done[b], 1u);
    __syncthreads();

    if (s_done != SEGS - 1) return;       // not the last CTA of this batch

    // ========== finisher CTA for batch b (wait-free: all others done) ======
    __threadfence();                      // acquire; single CTA, cheap

    // Each thread owns one 32-bit mask word = positions [t*32, t*32+32)
    unsigned w = __ldcg(&g_mask[b * WORDS + t]);
    int cnt = __popc(w);

    // Inclusive warp scan of per-word counts
    int inc = cnt;
#pragma unroll
    for (int d = 1; d < 32; d <<= 1) {
        int y = __shfl_up_sync(0xffffffffu, inc, d);
        if (lane >= d) inc += y;
    }

    __shared__ int s_wsum[8];
    if (lane == 31) s_wsum[wid] = inc;
    __syncthreads();

    if (wid == 0) {
        int wv = (lane < 8) ? s_wsum[lane] : 0;
        int winc = wv;
#pragma unroll
        for (int d = 1; d < 8; d <<= 1) {
            int y = __shfl_up_sync(0xffffffffu, winc, d);
            if (lane >= d) winc += y;
        }
        if (lane < 8) s_wsum[lane] = winc - wv;   // exclusive warp base
    }
    __syncthreads();

    int pos = s_wsum[wid] + (inc - cnt);          // exclusive thread base

    // Emit set-bit positions in ascending order (bitmask => sorted for free)
    float* oidx = out + (size_t)PB * PN + (size_t)b * PK;
    while (w) {
        int bit = __ffs(w) - 1;
        w &= w - 1;
        if (pos < PK) oidx[pos] = (float)(t * 32 + bit);
        pos++;
    }

    // ---- reset scratch for the next graph replay ----
    g_mask[b * WORDS + t] = 0u;
    if (t == 0) g_done[b] = 0u;
}

extern "C" void kernel_launch(void* const* d_in, const int* in_sizes, int n_in,
                              void* d_out, int out_size)
{
    const float* one_hot = (const float*)d_in[0];
    const int*   id_ptr  = (const int*)d_in[1];
    float*       out     = (float*)d_out;

    (void)in_sizes; (void)n_in; (void)out_size;

    fused_filter_kernel<<<PB * SEGS, TPB>>>(one_hot, id_ptr, out);
}